// round 3
// baseline (speedup 1.0000x reference)
#include <cuda_runtime.h>
#include <cuda_fp16.h>
#include <math.h>

#define NN 10000
#define EE 160000

// ---------------- scratch (device globals; no allocations allowed) ----------
__device__ float g_Q[NN * 64];
__device__ float g_K[NN * 64];
__device__ float g_V[NN * 64];
__device__ uint4 g_MA4[NN * 64];   // NN x 512 halfs (16B-aligned)
__device__ uint4 g_MB4[NN * 64];
__device__ float g_deginv[NN];
__device__ int   g_cnt[NN];
__device__ int   g_ptr[NN + 1];
__device__ int   g_wp[NN];
__device__ int   g_eidx[EE];   // edge id, sorted by destination then edge id
__device__ int   g_src[EE];    // source node per sorted position
__device__ float g_wt[EE];     // norm weight per sorted position

// ---------------- setup ------------------------------------------------------
__global__ void k_count(const int* __restrict__ col) {
    int e = blockIdx.x * blockDim.x + threadIdx.x;
    if (e < EE) atomicAdd(&g_cnt[col[e]], 1);
}

// single-block exclusive scan of g_cnt -> g_ptr / g_wp ; also deginv
__global__ void k_scan() {
    __shared__ int s[1024];
    int t = threadIdx.x;
    const int CH = (NN + 1023) / 1024;
    int start = t * CH;
    int sum = 0;
    for (int i = 0; i < CH; i++) {
        int idx = start + i;
        if (idx < NN) sum += g_cnt[idx];
    }
    s[t] = sum;
    __syncthreads();
    for (int off = 1; off < 1024; off <<= 1) {
        int v = (t >= off) ? s[t - off] : 0;
        __syncthreads();
        s[t] += v;
        __syncthreads();
    }
    int run = (t == 0) ? 0 : s[t - 1];
    for (int i = 0; i < CH; i++) {
        int idx = start + i;
        if (idx < NN) {
            int c = g_cnt[idx];
            g_ptr[idx] = run;
            g_wp[idx]  = run;
            g_deginv[idx] = (c > 0) ? rsqrtf((float)c) : 0.0f;
            run += c;
        }
    }
    if (t == 0) g_ptr[NN] = s[1023];
}

__global__ void k_place(const int* __restrict__ col) {
    int e = blockIdx.x * blockDim.x + threadIdx.x;
    if (e < EE) {
        int c = col[e];
        int p = atomicAdd(&g_wp[c], 1);
        g_eidx[p] = e;
    }
}

// sort each bucket ascending (deterministic order), then emit src/wt per slot
__global__ void k_sortgather(const int* __restrict__ row,
                             const float* __restrict__ ew) {
    int n = blockIdx.x * blockDim.x + threadIdx.x;
    if (n >= NN) return;
    int b = g_ptr[n], e2 = g_ptr[n + 1];
    for (int i = b + 1; i < e2; i++) {
        int v = g_eidx[i];
        int j = i - 1;
        while (j >= b && g_eidx[j] > v) {
            g_eidx[j + 1] = g_eidx[j];
            j--;
        }
        g_eidx[j + 1] = v;
    }
    float dc = g_deginv[n];
    for (int i = b; i < e2; i++) {
        int e = g_eidx[i];
        int r = __ldg(row + e);
        g_src[i] = r;
        g_wt[i]  = g_deginv[r] * dc * __ldg(ew + e);
    }
}

// ---------------- Q/K/V GEMM + hidden init ----------------------------------
__global__ void k_qkv(const float* __restrict__ x,
                      const float* __restrict__ Wq, const float* __restrict__ bq,
                      const float* __restrict__ Wk, const float* __restrict__ bk,
                      const float* __restrict__ Wv, const float* __restrict__ bv,
                      const float* __restrict__ hopwise, float* __restrict__ out) {
    __shared__ float sx[16 * 64];
    int n0 = blockIdx.x * 16;
    for (int idx = threadIdx.x; idx < 16 * 64; idx += 256)
        sx[idx] = x[(n0 + (idx >> 6)) * 64 + (idx & 63)];
    __syncthreads();

    int c = threadIdx.x & 63;
    int g = threadIdx.x >> 6;
    float aq[4] = {0, 0, 0, 0}, ak[4] = {0, 0, 0, 0}, av[4] = {0, 0, 0, 0};
#pragma unroll 4
    for (int k = 0; k < 64; k++) {
        float wq = Wq[k * 64 + c];
        float wk = Wk[k * 64 + c];
        float wv = Wv[k * 64 + c];
#pragma unroll
        for (int p = 0; p < 4; p++) {
            float xv = sx[(g + 4 * p) * 64 + k];
            aq[p] += xv * wq;
            ak[p] += xv * wk;
            av[p] += xv * wv;
        }
    }
    float hw0 = hopwise[0];
    float bqc = bq[c], bkc = bk[c], bvc = bv[c];
#pragma unroll
    for (int p = 0; p < 4; p++) {
        int n = n0 + g + 4 * p;
        g_Q[n * 64 + c] = fmaxf(aq[p] + bqc, 0.0f);
        g_K[n * 64 + c] = ak[p] + bkc;
        float v = av[p] + bvc;
        g_V[n * 64 + c] = v;
        out[n * 64 + c] = hw0 * v;
    }
}

// ---------------- fused epilogue: H = Q.M, normalize, out += hw*H ------------
// acc layout: lane owns h = lane>>2, i = (lane&3)*2 + {0,1}, all j (8).
__device__ __forceinline__ void h_epilogue(int n, int lane, const float* acc,
                                           float hw, float* __restrict__ out) {
    int h = lane >> 2;
    float2 q = *(const float2*)(g_Q + n * 64 + h * 8 + (lane & 3) * 2);
    float Hp[8];
#pragma unroll
    for (int j = 0; j < 8; j++) Hp[j] = q.x * acc[j] + q.y * acc[8 + j];
#pragma unroll
    for (int off = 1; off < 4; off <<= 1) {
#pragma unroll
        for (int j = 0; j < 8; j++)
            Hp[j] += __shfl_xor_sync(0xffffffffu, Hp[j], off);
    }
    float ss = 0.f;
#pragma unroll
    for (int j = 0; j < 8; j++) ss += Hp[j] * Hp[j];
    float nrm = sqrtf(ss * 0.125f);
    float sc = (nrm > 1.0f) ? (1.0f / nrm) : 1.0f;
    float c = hw * sc;
    if ((lane & 3) == 0) {
        float4* op = (float4*)(out + n * 64 + h * 8);
        float4 o0 = op[0], o1 = op[1];
        o0.x += c * Hp[0]; o0.y += c * Hp[1]; o0.z += c * Hp[2]; o0.w += c * Hp[3];
        o1.x += c * Hp[4]; o1.y += c * Hp[5]; o1.z += c * Hp[6]; o1.w += c * Hp[7];
        op[0] = o0; op[1] = o1;
    }
}

__device__ __forceinline__ void acc8(float* a, uint4 A, float w) {
    const __half2* h = (const __half2*)&A;
#pragma unroll
    for (int q = 0; q < 4; q++) {
        float2 f = __half22float2(h[q]);
        a[2 * q]     += w * f.x;
        a[2 * q + 1] += w * f.y;
    }
}

__device__ __forceinline__ void outer_acc(float* acc, float a0, float a1,
                                          float4 va, float4 vb) {
    acc[0]  += a0 * va.x; acc[1]  += a0 * va.y; acc[2]  += a0 * va.z; acc[3]  += a0 * va.w;
    acc[4]  += a0 * vb.x; acc[5]  += a0 * vb.y; acc[6]  += a0 * vb.z; acc[7]  += a0 * vb.w;
    acc[8]  += a1 * va.x; acc[9]  += a1 * va.y; acc[10] += a1 * va.z; acc[11] += a1 * va.w;
    acc[12] += a1 * vb.x; acc[13] += a1 * vb.y; acc[14] += a1 * vb.z; acc[15] += a1 * vb.w;
}

// ---------------- hop 0 + fused H-update -------------------------------------
__global__ void __launch_bounds__(256) k_hop0(const float* __restrict__ ef,
                                              const float* __restrict__ hopwise,
                                              float* __restrict__ out) {
    int warp = (blockIdx.x * blockDim.x + threadIdx.x) >> 5;
    if (warp >= NN) return;
    int lane = threadIdx.x & 31;
    int h8 = (lane >> 2) << 3;
    int i0 = (lane & 3) * 2;

    float acc[16];
#pragma unroll
    for (int t = 0; t < 16; t++) acc[t] = 0.0f;

    int beg = g_ptr[warp], end = g_ptr[warp + 1];
    int p = beg;
    for (; p + 4 <= end; p += 4) {
        float2 kk[4], ff[4];
        float4 va[4], vb[4];
        float w[4];
#pragma unroll
        for (int t = 0; t < 4; t++) {
            int e = g_eidx[p + t];
            int r = g_src[p + t];
            w[t] = g_wt[p + t];
            kk[t] = *(const float2*)(g_K + r * 64 + h8 + i0);
            ff[t] = *(const float2*)(ef + (size_t)e * 64 + h8 + i0);
            va[t] = *(const float4*)(g_V + r * 64 + h8);
            vb[t] = *(const float4*)(g_V + r * 64 + h8 + 4);
        }
#pragma unroll
        for (int t = 0; t < 4; t++) {
            float a0 = fmaxf(kk[t].x + ff[t].x, 0.0f) * w[t];
            float a1 = fmaxf(kk[t].y + ff[t].y, 0.0f) * w[t];
            outer_acc(acc, a0, a1, va[t], vb[t]);
        }
    }
    for (; p < end; p++) {
        int e = g_eidx[p];
        int r = g_src[p];
        float w0 = g_wt[p];
        float2 k0 = *(const float2*)(g_K + r * 64 + h8 + i0);
        float2 f0 = *(const float2*)(ef + (size_t)e * 64 + h8 + i0);
        float4 va0 = *(const float4*)(g_V + r * 64 + h8);
        float4 vb0 = *(const float4*)(g_V + r * 64 + h8 + 4);
        float a0 = fmaxf(k0.x + f0.x, 0.0f) * w0;
        float a1 = fmaxf(k0.y + f0.y, 0.0f) * w0;
        outer_acc(acc, a0, a1, va0, vb0);
    }

    // store M (fp16)
    uint4 o0, o1;
    __half2* ho0 = (__half2*)&o0;
    __half2* ho1 = (__half2*)&o1;
#pragma unroll
    for (int q = 0; q < 4; q++) {
        ho0[q] = __float22half2_rn(make_float2(acc[2 * q], acc[2 * q + 1]));
        ho1[q] = __float22half2_rn(make_float2(acc[8 + 2 * q], acc[8 + 2 * q + 1]));
    }
    uint4* dst = g_MA4 + (size_t)warp * 64 + lane * 2;
    dst[0] = o0; dst[1] = o1;

    h_epilogue(warp, lane, acc, __ldg(hopwise + 1), out);
}

// ---------------- prop hops + fused H-update ---------------------------------
__global__ void __launch_bounds__(256) k_prop(const uint4* __restrict__ Msrc,
                                              uint4* __restrict__ Mdst, int writeM,
                                              int hop, const float* __restrict__ hopwise,
                                              float* __restrict__ out) {
    int warp = (blockIdx.x * blockDim.x + threadIdx.x) >> 5;
    if (warp >= NN) return;
    int lane = threadIdx.x & 31;

    float acc[16];
#pragma unroll
    for (int t = 0; t < 16; t++) acc[t] = 0.0f;

    int beg = g_ptr[warp], end = g_ptr[warp + 1];
    int p = beg;
    // 8-edge software pipeline: 16 outstanding LDG.128 per lane
    for (; p + 8 <= end; p += 8) {
        uint4 A[16];
        float w[8];
#pragma unroll
        for (int t = 0; t < 8; t++) {
            int r = g_src[p + t];
            w[t] = g_wt[p + t];
            const uint4* m = Msrc + (size_t)r * 64 + lane * 2;
            A[2 * t]     = m[0];
            A[2 * t + 1] = m[1];
        }
#pragma unroll
        for (int t = 0; t < 8; t++) {
            acc8(acc,     A[2 * t],     w[t]);
            acc8(acc + 8, A[2 * t + 1], w[t]);
        }
    }
    for (; p + 2 <= end; p += 2) {
        int r0 = g_src[p], r1 = g_src[p + 1];
        float w0 = g_wt[p], w1 = g_wt[p + 1];
        const uint4* m0 = Msrc + (size_t)r0 * 64 + lane * 2;
        const uint4* m1 = Msrc + (size_t)r1 * 64 + lane * 2;
        uint4 A0 = m0[0], A1 = m0[1];
        uint4 B0 = m1[0], B1 = m1[1];
        acc8(acc, A0, w0); acc8(acc + 8, A1, w0);
        acc8(acc, B0, w1); acc8(acc + 8, B1, w1);
    }
    for (; p < end; p++) {
        int r0 = g_src[p];
        float w0 = g_wt[p];
        const uint4* m0 = Msrc + (size_t)r0 * 64 + lane * 2;
        uint4 A0 = m0[0], A1 = m0[1];
        acc8(acc, A0, w0); acc8(acc + 8, A1, w0);
    }

    if (writeM) {
        uint4 o0, o1;
        __half2* ho0 = (__half2*)&o0;
        __half2* ho1 = (__half2*)&o1;
#pragma unroll
        for (int q = 0; q < 4; q++) {
            ho0[q] = __float22half2_rn(make_float2(acc[2 * q], acc[2 * q + 1]));
            ho1[q] = __float22half2_rn(make_float2(acc[8 + 2 * q], acc[8 + 2 * q + 1]));
        }
        uint4* dst = Mdst + (size_t)warp * 64 + lane * 2;
        dst[0] = o0; dst[1] = o1;
    }

    h_epilogue(warp, lane, acc, __ldg(hopwise + hop), out);
}

// ---------------- launch -----------------------------------------------------
extern "C" void kernel_launch(void* const* d_in, const int* in_sizes, int n_in,
                              void* d_out, int out_size) {
    const float* x  = (const float*)d_in[0];
    const int*   ei = (const int*)d_in[1];
    const float* ef = (const float*)d_in[2];
    const float* ew = (const float*)d_in[3];
    const float* Wq = (const float*)d_in[4];
    const float* bq = (const float*)d_in[5];
    const float* Wk = (const float*)d_in[6];
    const float* bk = (const float*)d_in[7];
    const float* Wv = (const float*)d_in[8];
    const float* bv = (const float*)d_in[9];
    const float* hw = (const float*)d_in[10];
    const int* row = ei;
    const int* col = ei + EE;
    float* out = (float*)d_out;

    uint4 *dMA, *dMB;
    void* dcnt;
    cudaGetSymbolAddress((void**)&dMA, g_MA4);
    cudaGetSymbolAddress((void**)&dMB, g_MB4);
    cudaGetSymbolAddress(&dcnt, g_cnt);

    cudaMemsetAsync(dcnt, 0, NN * sizeof(int));
    k_count<<<(EE + 255) / 256, 256>>>(col);
    k_scan<<<1, 1024>>>();
    k_place<<<(EE + 255) / 256, 256>>>(col);
    k_sortgather<<<(NN + 255) / 256, 256>>>(row, ew);

    k_qkv<<<NN / 16, 256>>>(x, Wq, bq, Wk, bk, Wv, bv, hw, out);

    k_hop0<<<(NN * 32) / 256, 256>>>(ef, hw, out);                 // -> MA, out += hw[1]*H
    k_prop<<<(NN * 32) / 256, 256>>>(dMA, dMB, 1, 2, hw, out);     // MA -> MB, out += hw[2]*H
    k_prop<<<(NN * 32) / 256, 256>>>(dMB, dMA, 0, 3, hw, out);     // MB read-only, out += hw[3]*H
}

// round 4
// speedup vs baseline: 1.2274x; 1.2274x over previous
#include <cuda_runtime.h>
#include <cuda_fp16.h>
#include <math.h>

#define NN 10000
#define EE 160000

// ---------------- scratch (device globals; no allocations allowed) ----------
__device__ float g_Q[NN * 64];
__device__ float g_K[NN * 64];
__device__ float g_V[NN * 64];
__device__ uint4 g_MA4[NN * 64];   // NN x 512 halfs (16B-aligned)
__device__ uint4 g_MB4[NN * 64];
__device__ float g_deginv[NN];
__device__ int   g_cnt[NN];
__device__ int   g_ptr[NN + 1];
__device__ int   g_wp[NN];
__device__ int   g_eidx[EE];   // edge id, sorted by destination then edge id
__device__ int   g_src[EE];    // source node per sorted position
__device__ float g_wt[EE];     // norm weight per sorted position

// ---------------- setup ------------------------------------------------------
__global__ void k_count(const int* __restrict__ col) {
    int e = blockIdx.x * blockDim.x + threadIdx.x;
    if (e < EE) atomicAdd(&g_cnt[col[e]], 1);
}

// single-block exclusive scan of g_cnt -> g_ptr / g_wp ; also deginv
__global__ void k_scan() {
    __shared__ int s[1024];
    int t = threadIdx.x;
    const int CH = (NN + 1023) / 1024;
    int start = t * CH;
    int sum = 0;
    for (int i = 0; i < CH; i++) {
        int idx = start + i;
        if (idx < NN) sum += g_cnt[idx];
    }
    s[t] = sum;
    __syncthreads();
    for (int off = 1; off < 1024; off <<= 1) {
        int v = (t >= off) ? s[t - off] : 0;
        __syncthreads();
        s[t] += v;
        __syncthreads();
    }
    int run = (t == 0) ? 0 : s[t - 1];
    for (int i = 0; i < CH; i++) {
        int idx = start + i;
        if (idx < NN) {
            int c = g_cnt[idx];
            g_ptr[idx] = run;
            g_wp[idx]  = run;
            g_deginv[idx] = (c > 0) ? rsqrtf((float)c) : 0.0f;
            run += c;
        }
    }
    if (t == 0) g_ptr[NN] = s[1023];
}

__global__ void k_place(const int* __restrict__ col) {
    int e = blockIdx.x * blockDim.x + threadIdx.x;
    if (e < EE) {
        int c = col[e];
        int p = atomicAdd(&g_wp[c], 1);
        g_eidx[p] = e;
    }
}

// warp per node: bitonic-sort bucket (deterministic order), gather src/wt in parallel
__global__ void __launch_bounds__(256) k_sortgather(const int* __restrict__ row,
                                                    const float* __restrict__ ew) {
    int n = (blockIdx.x * blockDim.x + threadIdx.x) >> 5;
    if (n >= NN) return;
    int lane = threadIdx.x & 31;
    int b = g_ptr[n], e2 = g_ptr[n + 1];
    int d = e2 - b;
    if (d <= 0) return;
    float dc = g_deginv[n];

    if (d <= 32) {
        int v = (lane < d) ? g_eidx[b + lane] : 0x7fffffff;
        // 32-element bitonic sort via shfl_xor
#pragma unroll
        for (int k = 2; k <= 32; k <<= 1) {
#pragma unroll
            for (int j = k >> 1; j > 0; j >>= 1) {
                int other = __shfl_xor_sync(0xffffffffu, v, j);
                bool higher = (lane & j) != 0;
                bool asc = (lane & k) == 0;
                v = (higher == asc) ? max(v, other) : min(v, other);
            }
        }
        if (lane < d) {
            g_eidx[b + lane] = v;
            int r = __ldg(row + v);
            g_src[b + lane] = r;
            g_wt[b + lane]  = g_deginv[r] * dc * __ldg(ew + v);
        }
    } else {
        // rare (Poisson(16) tail): lane 0 serial insertion sort, then parallel gather
        if (lane == 0) {
            for (int i = b + 1; i < e2; i++) {
                int v = g_eidx[i];
                int j = i - 1;
                while (j >= b && g_eidx[j] > v) {
                    g_eidx[j + 1] = g_eidx[j];
                    j--;
                }
                g_eidx[j + 1] = v;
            }
        }
        __syncwarp();
        for (int i = b + lane; i < e2; i += 32) {
            int e = g_eidx[i];
            int r = __ldg(row + e);
            g_src[i] = r;
            g_wt[i]  = g_deginv[r] * dc * __ldg(ew + e);
        }
    }
}

// ---------------- Q/K/V GEMM + hidden init ----------------------------------
__global__ void k_qkv(const float* __restrict__ x,
                      const float* __restrict__ Wq, const float* __restrict__ bq,
                      const float* __restrict__ Wk, const float* __restrict__ bk,
                      const float* __restrict__ Wv, const float* __restrict__ bv,
                      const float* __restrict__ hopwise, float* __restrict__ out) {
    __shared__ float sx[16 * 64];
    int n0 = blockIdx.x * 16;
    for (int idx = threadIdx.x; idx < 16 * 64; idx += 256)
        sx[idx] = x[(n0 + (idx >> 6)) * 64 + (idx & 63)];
    __syncthreads();

    int c = threadIdx.x & 63;
    int g = threadIdx.x >> 6;
    float aq[4] = {0, 0, 0, 0}, ak[4] = {0, 0, 0, 0}, av[4] = {0, 0, 0, 0};
#pragma unroll 4
    for (int k = 0; k < 64; k++) {
        float wq = Wq[k * 64 + c];
        float wk = Wk[k * 64 + c];
        float wv = Wv[k * 64 + c];
#pragma unroll
        for (int p = 0; p < 4; p++) {
            float xv = sx[(g + 4 * p) * 64 + k];
            aq[p] += xv * wq;
            ak[p] += xv * wk;
            av[p] += xv * wv;
        }
    }
    float hw0 = hopwise[0];
    float bqc = bq[c], bkc = bk[c], bvc = bv[c];
#pragma unroll
    for (int p = 0; p < 4; p++) {
        int n = n0 + g + 4 * p;
        g_Q[n * 64 + c] = fmaxf(aq[p] + bqc, 0.0f);
        g_K[n * 64 + c] = ak[p] + bkc;
        float v = av[p] + bvc;
        g_V[n * 64 + c] = v;
        out[n * 64 + c] = hw0 * v;
    }
}

// ---------------- fused epilogue: H = Q.M, normalize, out += hw*H ------------
// acc layout: lane owns h = lane>>2, i = (lane&3)*2 + {0,1}, all j (8).
__device__ __forceinline__ void h_epilogue(int n, int lane, const float* acc,
                                           float hw, float* __restrict__ out) {
    int h = lane >> 2;
    float2 q = *(const float2*)(g_Q + n * 64 + h * 8 + (lane & 3) * 2);
    float Hp[8];
#pragma unroll
    for (int j = 0; j < 8; j++) Hp[j] = q.x * acc[j] + q.y * acc[8 + j];
#pragma unroll
    for (int off = 1; off < 4; off <<= 1) {
#pragma unroll
        for (int j = 0; j < 8; j++)
            Hp[j] += __shfl_xor_sync(0xffffffffu, Hp[j], off);
    }
    float ss = 0.f;
#pragma unroll
    for (int j = 0; j < 8; j++) ss += Hp[j] * Hp[j];
    float nrm = sqrtf(ss * 0.125f);
    float sc = (nrm > 1.0f) ? (1.0f / nrm) : 1.0f;
    float c = hw * sc;
    if ((lane & 3) == 0) {
        float4* op = (float4*)(out + n * 64 + h * 8);
        float4 o0 = op[0], o1 = op[1];
        o0.x += c * Hp[0]; o0.y += c * Hp[1]; o0.z += c * Hp[2]; o0.w += c * Hp[3];
        o1.x += c * Hp[4]; o1.y += c * Hp[5]; o1.z += c * Hp[6]; o1.w += c * Hp[7];
        op[0] = o0; op[1] = o1;
    }
}

__device__ __forceinline__ void acc8(float* a, uint4 A, float w) {
    const __half2* h = (const __half2*)&A;
#pragma unroll
    for (int q = 0; q < 4; q++) {
        float2 f = __half22float2(h[q]);
        a[2 * q]     += w * f.x;
        a[2 * q + 1] += w * f.y;
    }
}

__device__ __forceinline__ void outer_acc(float* acc, float a0, float a1,
                                          float4 va, float4 vb) {
    acc[0]  += a0 * va.x; acc[1]  += a0 * va.y; acc[2]  += a0 * va.z; acc[3]  += a0 * va.w;
    acc[4]  += a0 * vb.x; acc[5]  += a0 * vb.y; acc[6]  += a0 * vb.z; acc[7]  += a0 * vb.w;
    acc[8]  += a1 * va.x; acc[9]  += a1 * va.y; acc[10] += a1 * va.z; acc[11] += a1 * va.w;
    acc[12] += a1 * vb.x; acc[13] += a1 * vb.y; acc[14] += a1 * vb.z; acc[15] += a1 * vb.w;
}

// ---------------- hop 0 + fused H-update -------------------------------------
__global__ void __launch_bounds__(256) k_hop0(const float* __restrict__ ef,
                                              const float* __restrict__ hopwise,
                                              float* __restrict__ out) {
    int warp = (blockIdx.x * blockDim.x + threadIdx.x) >> 5;
    if (warp >= NN) return;
    int lane = threadIdx.x & 31;
    int h8 = (lane >> 2) << 3;
    int i0 = (lane & 3) * 2;

    float acc[16];
#pragma unroll
    for (int t = 0; t < 16; t++) acc[t] = 0.0f;

    int beg = g_ptr[warp], end = g_ptr[warp + 1];
    int p = beg;
    for (; p + 4 <= end; p += 4) {
        float2 kk[4], ff[4];
        float4 va[4], vb[4];
        float w[4];
#pragma unroll
        for (int t = 0; t < 4; t++) {
            int e = g_eidx[p + t];
            int r = g_src[p + t];
            w[t] = g_wt[p + t];
            kk[t] = *(const float2*)(g_K + r * 64 + h8 + i0);
            ff[t] = *(const float2*)(ef + (size_t)e * 64 + h8 + i0);
            va[t] = *(const float4*)(g_V + r * 64 + h8);
            vb[t] = *(const float4*)(g_V + r * 64 + h8 + 4);
        }
#pragma unroll
        for (int t = 0; t < 4; t++) {
            float a0 = fmaxf(kk[t].x + ff[t].x, 0.0f) * w[t];
            float a1 = fmaxf(kk[t].y + ff[t].y, 0.0f) * w[t];
            outer_acc(acc, a0, a1, va[t], vb[t]);
        }
    }
    for (; p < end; p++) {
        int e = g_eidx[p];
        int r = g_src[p];
        float w0 = g_wt[p];
        float2 k0 = *(const float2*)(g_K + r * 64 + h8 + i0);
        float2 f0 = *(const float2*)(ef + (size_t)e * 64 + h8 + i0);
        float4 va0 = *(const float4*)(g_V + r * 64 + h8);
        float4 vb0 = *(const float4*)(g_V + r * 64 + h8 + 4);
        float a0 = fmaxf(k0.x + f0.x, 0.0f) * w0;
        float a1 = fmaxf(k0.y + f0.y, 0.0f) * w0;
        outer_acc(acc, a0, a1, va0, vb0);
    }

    // store M (fp16)
    uint4 o0, o1;
    __half2* ho0 = (__half2*)&o0;
    __half2* ho1 = (__half2*)&o1;
#pragma unroll
    for (int q = 0; q < 4; q++) {
        ho0[q] = __float22half2_rn(make_float2(acc[2 * q], acc[2 * q + 1]));
        ho1[q] = __float22half2_rn(make_float2(acc[8 + 2 * q], acc[8 + 2 * q + 1]));
    }
    uint4* dst = g_MA4 + (size_t)warp * 64 + lane * 2;
    dst[0] = o0; dst[1] = o1;

    h_epilogue(warp, lane, acc, __ldg(hopwise + 1), out);
}

// ---------------- prop hops + fused H-update ---------------------------------
__global__ void __launch_bounds__(256) k_prop(const uint4* __restrict__ Msrc,
                                              uint4* __restrict__ Mdst, int writeM,
                                              int hop, const float* __restrict__ hopwise,
                                              float* __restrict__ out) {
    int warp = (blockIdx.x * blockDim.x + threadIdx.x) >> 5;
    if (warp >= NN) return;
    int lane = threadIdx.x & 31;

    float acc[16];
#pragma unroll
    for (int t = 0; t < 16; t++) acc[t] = 0.0f;

    int beg = g_ptr[warp], end = g_ptr[warp + 1];
    int p = beg;
    // 8-edge software pipeline: 16 outstanding LDG.128 per lane
    for (; p + 8 <= end; p += 8) {
        uint4 A[16];
        float w[8];
#pragma unroll
        for (int t = 0; t < 8; t++) {
            int r = g_src[p + t];
            w[t] = g_wt[p + t];
            const uint4* m = Msrc + (size_t)r * 64 + lane * 2;
            A[2 * t]     = m[0];
            A[2 * t + 1] = m[1];
        }
#pragma unroll
        for (int t = 0; t < 8; t++) {
            acc8(acc,     A[2 * t],     w[t]);
            acc8(acc + 8, A[2 * t + 1], w[t]);
        }
    }
    for (; p + 2 <= end; p += 2) {
        int r0 = g_src[p], r1 = g_src[p + 1];
        float w0 = g_wt[p], w1 = g_wt[p + 1];
        const uint4* m0 = Msrc + (size_t)r0 * 64 + lane * 2;
        const uint4* m1 = Msrc + (size_t)r1 * 64 + lane * 2;
        uint4 A0 = m0[0], A1 = m0[1];
        uint4 B0 = m1[0], B1 = m1[1];
        acc8(acc, A0, w0); acc8(acc + 8, A1, w0);
        acc8(acc, B0, w1); acc8(acc + 8, B1, w1);
    }
    for (; p < end; p++) {
        int r0 = g_src[p];
        float w0 = g_wt[p];
        const uint4* m0 = Msrc + (size_t)r0 * 64 + lane * 2;
        uint4 A0 = m0[0], A1 = m0[1];
        acc8(acc, A0, w0); acc8(acc + 8, A1, w0);
    }

    if (writeM) {
        uint4 o0, o1;
        __half2* ho0 = (__half2*)&o0;
        __half2* ho1 = (__half2*)&o1;
#pragma unroll
        for (int q = 0; q < 4; q++) {
            ho0[q] = __float22half2_rn(make_float2(acc[2 * q], acc[2 * q + 1]));
            ho1[q] = __float22half2_rn(make_float2(acc[8 + 2 * q], acc[8 + 2 * q + 1]));
        }
        uint4* dst = Mdst + (size_t)warp * 64 + lane * 2;
        dst[0] = o0; dst[1] = o1;
    }

    h_epilogue(warp, lane, acc, __ldg(hopwise + hop), out);
}

// ---------------- launch -----------------------------------------------------
extern "C" void kernel_launch(void* const* d_in, const int* in_sizes, int n_in,
                              void* d_out, int out_size) {
    const float* x  = (const float*)d_in[0];
    const int*   ei = (const int*)d_in[1];
    const float* ef = (const float*)d_in[2];
    const float* ew = (const float*)d_in[3];
    const float* Wq = (const float*)d_in[4];
    const float* bq = (const float*)d_in[5];
    const float* Wk = (const float*)d_in[6];
    const float* bk = (const float*)d_in[7];
    const float* Wv = (const float*)d_in[8];
    const float* bv = (const float*)d_in[9];
    const float* hw = (const float*)d_in[10];
    const int* row = ei;
    const int* col = ei + EE;
    float* out = (float*)d_out;

    uint4 *dMA, *dMB;
    void* dcnt;
    cudaGetSymbolAddress((void**)&dMA, g_MA4);
    cudaGetSymbolAddress((void**)&dMB, g_MB4);
    cudaGetSymbolAddress(&dcnt, g_cnt);

    cudaMemsetAsync(dcnt, 0, NN * sizeof(int));
    k_count<<<(EE + 255) / 256, 256>>>(col);
    k_scan<<<1, 1024>>>();
    k_place<<<(EE + 255) / 256, 256>>>(col);
    k_sortgather<<<(NN * 32 + 255) / 256, 256>>>(row, ew);

    k_qkv<<<NN / 16, 256>>>(x, Wq, bq, Wk, bk, Wv, bv, hw, out);

    k_hop0<<<(NN * 32) / 256, 256>>>(ef, hw, out);                 // -> MA, out += hw[1]*H
    k_prop<<<(NN * 32) / 256, 256>>>(dMA, dMB, 1, 2, hw, out);     // MA -> MB, out += hw[2]*H
    k_prop<<<(NN * 32) / 256, 256>>>(dMB, dMA, 0, 3, hw, out);     // MB read-only, out += hw[3]*H
}

// round 5
// speedup vs baseline: 1.2459x; 1.0150x over previous
#include <cuda_runtime.h>
#include <cuda_fp16.h>
#include <math.h>

#define NN 10000
#define EE 160000

// ---------------- scratch (device globals; no allocations allowed) ----------
__device__ float g_Q[NN * 64];
__device__ float g_K[NN * 64];
__device__ float g_V[NN * 64];
__device__ uint4 g_MA4[NN * 64];   // NN x 512 halfs (16B-aligned)
__device__ uint4 g_MB4[NN * 64];
__device__ float g_deginv[NN];
__device__ int   g_cnt[NN];
__device__ int   g_ptr[NN + 1];
__device__ int   g_wp[NN];
__device__ int   g_eidx[EE];   // edge id, sorted by destination then edge id
__device__ int   g_src[EE];    // source node per sorted position
__device__ float g_wt[EE];     // norm weight per sorted position

// ---------------- setup ------------------------------------------------------
__global__ void k_count(const int* __restrict__ col) {
    int e = blockIdx.x * blockDim.x + threadIdx.x;
    if (e < EE) atomicAdd(&g_cnt[col[e]], 1);
}

// single-block exclusive scan of g_cnt -> g_ptr / g_wp ; also deginv
__global__ void k_scan() {
    __shared__ int s[1024];
    int t = threadIdx.x;
    const int CH = (NN + 1023) / 1024;
    int start = t * CH;
    int sum = 0;
    for (int i = 0; i < CH; i++) {
        int idx = start + i;
        if (idx < NN) sum += g_cnt[idx];
    }
    s[t] = sum;
    __syncthreads();
    for (int off = 1; off < 1024; off <<= 1) {
        int v = (t >= off) ? s[t - off] : 0;
        __syncthreads();
        s[t] += v;
        __syncthreads();
    }
    int run = (t == 0) ? 0 : s[t - 1];
    for (int i = 0; i < CH; i++) {
        int idx = start + i;
        if (idx < NN) {
            int c = g_cnt[idx];
            g_ptr[idx] = run;
            g_wp[idx]  = run;
            g_deginv[idx] = (c > 0) ? rsqrtf((float)c) : 0.0f;
            run += c;
        }
    }
    if (t == 0) g_ptr[NN] = s[1023];
}

__global__ void k_place(const int* __restrict__ col) {
    int e = blockIdx.x * blockDim.x + threadIdx.x;
    if (e < EE) {
        int c = col[e];
        int p = atomicAdd(&g_wp[c], 1);
        g_eidx[p] = e;
    }
}

// warp per node: sort bucket (deterministic order), gather src/wt in parallel
__global__ void __launch_bounds__(256) k_sortgather(const int* __restrict__ row,
                                                    const float* __restrict__ ew) {
    __shared__ int sbuf[8][128];
    int n = (blockIdx.x * blockDim.x + threadIdx.x) >> 5;
    if (n >= NN) return;
    int lane = threadIdx.x & 31;
    int b = g_ptr[n], e2 = g_ptr[n + 1];
    int d = e2 - b;
    if (d <= 0) return;
    float dc = g_deginv[n];

    if (d <= 32) {
        int v = (lane < d) ? g_eidx[b + lane] : 0x7fffffff;
        // 32-element bitonic sort via shfl_xor
#pragma unroll
        for (int k = 2; k <= 32; k <<= 1) {
#pragma unroll
            for (int j = k >> 1; j > 0; j >>= 1) {
                int other = __shfl_xor_sync(0xffffffffu, v, j);
                bool higher = (lane & j) != 0;
                bool asc = (lane & k) == 0;
                v = (higher == asc) ? max(v, other) : min(v, other);
            }
        }
        if (lane < d) {
            g_eidx[b + lane] = v;
            int r = __ldg(row + v);
            g_src[b + lane] = r;
            g_wt[b + lane]  = g_deginv[r] * dc * __ldg(ew + v);
        }
    } else if (d <= 128) {
        // warp-parallel odd-even transposition sort in shared memory
        int* s = sbuf[(threadIdx.x >> 5)];
        for (int i = lane; i < d; i += 32) s[i] = g_eidx[b + i];
        __syncwarp();
        for (int ph = 0; ph < d; ph++) {
            int startp = ph & 1;
            for (int i = startp + 2 * lane; i + 1 < d; i += 64) {
                int a = s[i], c = s[i + 1];
                if (a > c) { s[i] = c; s[i + 1] = a; }
            }
            __syncwarp();
        }
        for (int i = lane; i < d; i += 32) {
            int e = s[i];
            g_eidx[b + i] = e;
            int r = __ldg(row + e);
            g_src[b + i] = r;
            g_wt[b + i]  = g_deginv[r] * dc * __ldg(ew + e);
        }
    } else {
        // essentially unreachable for this data; correctness fallback
        if (lane == 0) {
            for (int i = b + 1; i < e2; i++) {
                int v = g_eidx[i];
                int j = i - 1;
                while (j >= b && g_eidx[j] > v) {
                    g_eidx[j + 1] = g_eidx[j];
                    j--;
                }
                g_eidx[j + 1] = v;
            }
        }
        __syncwarp();
        for (int i = b + lane; i < e2; i += 32) {
            int e = g_eidx[i];
            int r = __ldg(row + e);
            g_src[i] = r;
            g_wt[i]  = g_deginv[r] * dc * __ldg(ew + e);
        }
    }
}

// ---------------- Q/K/V GEMM + hidden init ----------------------------------
__global__ void k_qkv(const float* __restrict__ x,
                      const float* __restrict__ Wq, const float* __restrict__ bq,
                      const float* __restrict__ Wk, const float* __restrict__ bk,
                      const float* __restrict__ Wv, const float* __restrict__ bv,
                      const float* __restrict__ hopwise, float* __restrict__ out) {
    __shared__ float sx[16 * 64];
    int n0 = blockIdx.x * 16;
    for (int idx = threadIdx.x; idx < 16 * 64; idx += 256)
        sx[idx] = x[(n0 + (idx >> 6)) * 64 + (idx & 63)];
    __syncthreads();

    int c = threadIdx.x & 63;
    int g = threadIdx.x >> 6;
    float aq[4] = {0, 0, 0, 0}, ak[4] = {0, 0, 0, 0}, av[4] = {0, 0, 0, 0};
#pragma unroll 4
    for (int k = 0; k < 64; k++) {
        float wq = Wq[k * 64 + c];
        float wk = Wk[k * 64 + c];
        float wv = Wv[k * 64 + c];
#pragma unroll
        for (int p = 0; p < 4; p++) {
            float xv = sx[(g + 4 * p) * 64 + k];
            aq[p] += xv * wq;
            ak[p] += xv * wk;
            av[p] += xv * wv;
        }
    }
    float hw0 = hopwise[0];
    float bqc = bq[c], bkc = bk[c], bvc = bv[c];
#pragma unroll
    for (int p = 0; p < 4; p++) {
        int n = n0 + g + 4 * p;
        g_Q[n * 64 + c] = fmaxf(aq[p] + bqc, 0.0f);
        g_K[n * 64 + c] = ak[p] + bkc;
        float v = av[p] + bvc;
        g_V[n * 64 + c] = v;
        out[n * 64 + c] = hw0 * v;
    }
}

// ---------------- fused epilogue (64 threads/node) ---------------------------
// thread t (0..63) owns (h = t>>3, i = t&7), acc[8] = j values of M[h,i,:]
__device__ __forceinline__ void h_epilogue64(int n, int t, const float* acc,
                                             float hw, float* __restrict__ out) {
    float q = g_Q[n * 64 + t];   // Q[n,h,i]
    float Hp[8];
#pragma unroll
    for (int j = 0; j < 8; j++) Hp[j] = q * acc[j];
#pragma unroll
    for (int off = 1; off < 8; off <<= 1) {
#pragma unroll
        for (int j = 0; j < 8; j++)
            Hp[j] += __shfl_xor_sync(0xffffffffu, Hp[j], off);
    }
    if ((t & 7) == 0) {
        float ss = 0.f;
#pragma unroll
        for (int j = 0; j < 8; j++) ss += Hp[j] * Hp[j];
        float nrm = sqrtf(ss * 0.125f);
        float sc = (nrm > 1.0f) ? (1.0f / nrm) : 1.0f;
        float c = hw * sc;
        int h = t >> 3;
        float4* op = (float4*)(out + n * 64 + h * 8);
        float4 o0 = op[0], o1 = op[1];
        o0.x += c * Hp[0]; o0.y += c * Hp[1]; o0.z += c * Hp[2]; o0.w += c * Hp[3];
        o1.x += c * Hp[4]; o1.y += c * Hp[5]; o1.z += c * Hp[6]; o1.w += c * Hp[7];
        op[0] = o0; op[1] = o1;
    }
}

__device__ __forceinline__ void acc8(float* a, uint4 A, float w) {
    const __half2* h = (const __half2*)&A;
#pragma unroll
    for (int q = 0; q < 4; q++) {
        float2 f = __half22float2(h[q]);
        a[2 * q]     += w * f.x;
        a[2 * q + 1] += w * f.y;
    }
}

__device__ __forceinline__ uint4 pack8(const float* a) {
    uint4 o;
    __half2* ho = (__half2*)&o;
#pragma unroll
    for (int q = 0; q < 4; q++)
        ho[q] = __float22half2_rn(make_float2(a[2 * q], a[2 * q + 1]));
    return o;
}

// ---------------- hop 0 + fused H-update (64 threads/node) -------------------
__global__ void __launch_bounds__(256) k_hop0(const float* __restrict__ ef,
                                              const float* __restrict__ hopwise,
                                              float* __restrict__ out) {
    int node = blockIdx.x * 4 + (threadIdx.x >> 6);
    if (node >= NN) return;
    int t = threadIdx.x & 63;
    int h8 = (t >> 3) << 3;

    float acc[8];
#pragma unroll
    for (int j = 0; j < 8; j++) acc[j] = 0.0f;

    int beg = g_ptr[node], end = g_ptr[node + 1];
    int p = beg;
    for (; p + 4 <= end; p += 4) {
        float kv[4], fv[4], w[4];
        float4 va[4], vb[4];
#pragma unroll
        for (int q = 0; q < 4; q++) {
            int e = g_eidx[p + q];
            int r = g_src[p + q];
            w[q]  = g_wt[p + q];
            kv[q] = g_K[r * 64 + t];
            fv[q] = ef[(size_t)e * 64 + t];
            va[q] = *(const float4*)(g_V + r * 64 + h8);
            vb[q] = *(const float4*)(g_V + r * 64 + h8 + 4);
        }
#pragma unroll
        for (int q = 0; q < 4; q++) {
            float a = fmaxf(kv[q] + fv[q], 0.0f) * w[q];
            acc[0] += a * va[q].x; acc[1] += a * va[q].y;
            acc[2] += a * va[q].z; acc[3] += a * va[q].w;
            acc[4] += a * vb[q].x; acc[5] += a * vb[q].y;
            acc[6] += a * vb[q].z; acc[7] += a * vb[q].w;
        }
    }
    for (; p < end; p++) {
        int e = g_eidx[p];
        int r = g_src[p];
        float w0 = g_wt[p];
        float kv = g_K[r * 64 + t];
        float fv = ef[(size_t)e * 64 + t];
        float4 va = *(const float4*)(g_V + r * 64 + h8);
        float4 vb = *(const float4*)(g_V + r * 64 + h8 + 4);
        float a = fmaxf(kv + fv, 0.0f) * w0;
        acc[0] += a * va.x; acc[1] += a * va.y; acc[2] += a * va.z; acc[3] += a * va.w;
        acc[4] += a * vb.x; acc[5] += a * vb.y; acc[6] += a * vb.z; acc[7] += a * vb.w;
    }

    g_MA4[(size_t)node * 64 + t] = pack8(acc);
    h_epilogue64(node, t, acc, __ldg(hopwise + 1), out);
}

// ---------------- prop hops + fused H-update (64 threads/node) ---------------
__global__ void __launch_bounds__(256) k_prop(const uint4* __restrict__ Msrc,
                                              uint4* __restrict__ Mdst, int writeM,
                                              int hop, const float* __restrict__ hopwise,
                                              float* __restrict__ out) {
    int node = blockIdx.x * 4 + (threadIdx.x >> 6);
    if (node >= NN) return;
    int t = threadIdx.x & 63;

    float acc[8];
#pragma unroll
    for (int j = 0; j < 8; j++) acc[j] = 0.0f;

    int beg = g_ptr[node], end = g_ptr[node + 1];
    int p = beg;
    // 8-edge software pipeline: 8 outstanding LDG.128 per lane
    for (; p + 8 <= end; p += 8) {
        uint4 A[8];
        float w[8];
#pragma unroll
        for (int q = 0; q < 8; q++) {
            int r = g_src[p + q];
            w[q] = g_wt[p + q];
            A[q] = Msrc[(size_t)r * 64 + t];
        }
#pragma unroll
        for (int q = 0; q < 8; q++) acc8(acc, A[q], w[q]);
    }
    for (; p + 4 <= end; p += 4) {
        uint4 A[4];
        float w[4];
#pragma unroll
        for (int q = 0; q < 4; q++) {
            int r = g_src[p + q];
            w[q] = g_wt[p + q];
            A[q] = Msrc[(size_t)r * 64 + t];
        }
#pragma unroll
        for (int q = 0; q < 4; q++) acc8(acc, A[q], w[q]);
    }
    for (; p < end; p++) {
        int r = g_src[p];
        float w0 = g_wt[p];
        uint4 A = Msrc[(size_t)r * 64 + t];
        acc8(acc, A, w0);
    }

    if (writeM) Mdst[(size_t)node * 64 + t] = pack8(acc);
    h_epilogue64(node, t, acc, __ldg(hopwise + hop), out);
}

// ---------------- launch -----------------------------------------------------
extern "C" void kernel_launch(void* const* d_in, const int* in_sizes, int n_in,
                              void* d_out, int out_size) {
    const float* x  = (const float*)d_in[0];
    const int*   ei = (const int*)d_in[1];
    const float* ef = (const float*)d_in[2];
    const float* ew = (const float*)d_in[3];
    const float* Wq = (const float*)d_in[4];
    const float* bq = (const float*)d_in[5];
    const float* Wk = (const float*)d_in[6];
    const float* bk = (const float*)d_in[7];
    const float* Wv = (const float*)d_in[8];
    const float* bv = (const float*)d_in[9];
    const float* hw = (const float*)d_in[10];
    const int* row = ei;
    const int* col = ei + EE;
    float* out = (float*)d_out;

    uint4 *dMA, *dMB;
    void* dcnt;
    cudaGetSymbolAddress((void**)&dMA, g_MA4);
    cudaGetSymbolAddress((void**)&dMB, g_MB4);
    cudaGetSymbolAddress(&dcnt, g_cnt);

    cudaMemsetAsync(dcnt, 0, NN * sizeof(int));
    k_count<<<(EE + 255) / 256, 256>>>(col);
    k_scan<<<1, 1024>>>();
    k_place<<<(EE + 255) / 256, 256>>>(col);
    k_sortgather<<<(NN * 32 + 255) / 256, 256>>>(row, ew);

    k_qkv<<<NN / 16, 256>>>(x, Wq, bq, Wk, bk, Wv, bv, hw, out);

    k_hop0<<<2500, 256>>>(ef, hw, out);                  // -> MA, out += hw[1]*H
    k_prop<<<2500, 256>>>(dMA, dMB, 1, 2, hw, out);      // MA -> MB, out += hw[2]*H
    k_prop<<<2500, 256>>>(dMB, dMA, 0, 3, hw, out);      // MB read-only, out += hw[3]*H
}